// round 11
// baseline (speedup 1.0000x reference)
#include <cuda_runtime.h>
#include <math.h>

#define B_   16
#define T_   128
#define I_   256
#define H_   256
#define NZ_  1024          // 4*H
#define NBLK 128           // 4 groups x 32 blocks
#define GRPB 32            // blocks per group
#define ARRV (GRPB * 8)    // arrivals per step: one per WARP (32 blocks x 8)

typedef unsigned long long ull;

// Scratch (static device globals: no allocation)
__device__ float    g_xz[T_ * NZ_ * B_];   // [t][n][b]  8 MB
__device__ float    g_h[2][B_ * H_];       // ping-pong hidden state [b][u]
__device__ unsigned g_arr[4 * T_ * 8];     // per-(group,step) counters, 32B apart

// fast transcendentals: ex2.approx + rcp.approx (~1e-6 rel err each)
__device__ __forceinline__ float fsigmoid(float x) {
    float e; asm("ex2.approx.ftz.f32 %0, %1;" : "=f"(e) : "f"(-1.4426950408889634f * x));
    float r; asm("rcp.approx.ftz.f32 %0, %1;" : "=f"(r) : "f"(1.0f + e));
    return r;
}
__device__ __forceinline__ float ftanh_(float x) {
    x = fminf(fmaxf(x, -30.0f), 30.0f);
    float e; asm("ex2.approx.ftz.f32 %0, %1;" : "=f"(e) : "f"(2.8853900817779268f * x));
    float r; asm("rcp.approx.ftz.f32 %0, %1;" : "=f"(r) : "f"(e + 1.0f));
    return (e - 1.0f) * r;
}

// packed f32x2 helpers (sm_100+)
__device__ __forceinline__ ull pack2(float lo, float hi) {
    ull r; asm("mov.b64 %0, {%1,%2};" : "=l"(r) : "f"(lo), "f"(hi)); return r;
}
__device__ __forceinline__ void unpack2(ull v, float& lo, float& hi) {
    asm("mov.b64 {%0,%1}, %2;" : "=f"(lo), "=f"(hi) : "l"(v));
}
__device__ __forceinline__ ull fma2(ull a, ull b, ull c) {
    ull d; asm("fma.rn.f32x2 %0, %1, %2, %3;" : "=l"(d) : "l"(a), "l"(b), "l"(c));
    return d;
}

// ---------------------------------------------------------------------------
// Kernel 1: XZ[t][n][b] = sum_k x[b][t][k] * Wih[k][n]   (k < 256 rows of Wih)
// grid (8 n-blocks of 128 cols, 128 t), 128 threads
// Also resets the group counters (graph-replay safe: runs before kernel 2).
// ---------------------------------------------------------------------------
__global__ void __launch_bounds__(128)
xz_kernel(const float* __restrict__ x, const float* __restrict__ Wih)
{
    if (blockIdx.y == 0) {
        int base = (blockIdx.x * 128 + threadIdx.x) * 4;   // 1024 thr x 4 = 4096
        #pragma unroll
        for (int i = 0; i < 4; i++) g_arr[base + i] = 0u;
    }

    __shared__ float x_s[I_ * B_];     // [k][b], 16 KB
    __shared__ float w_s[16 * 128];    // one 16-row k-panel of Wih cols n0..n0+127

    const int t   = blockIdx.y;
    const int n0  = blockIdx.x * 128;
    const int tid = threadIdx.x;

    for (int idx = tid; idx < B_ * I_; idx += 128) {
        int b = idx >> 8;
        int k = idx & 255;
        x_s[k * B_ + b] = x[(b * T_ + t) * I_ + k];
    }

    const int bq = tid >> 5;
    const int ng = tid & 31;
    const int b0 = bq * 4;
    const int nn = ng * 4;

    float acc[4][4];
    #pragma unroll
    for (int i = 0; i < 4; i++)
        #pragma unroll
        for (int j = 0; j < 4; j++) acc[i][j] = 0.f;

    for (int kb = 0; kb < 16; kb++) {
        __syncthreads();
        for (int q = tid; q < 512; q += 128) {
            int r  = q >> 5;
            int c4 = q & 31;
            ((float4*)w_s)[q] =
                ((const float4*)(Wih + (size_t)(kb * 16 + r) * NZ_ + n0))[c4];
        }
        __syncthreads();
        #pragma unroll
        for (int kk = 0; kk < 16; kk++) {
            float4 xv = *(const float4*)&x_s[(kb * 16 + kk) * B_ + b0];
            float4 wv = *(const float4*)&w_s[kk * 128 + nn];
            float xr[4] = {xv.x, xv.y, xv.z, xv.w};
            float wr_[4] = {wv.x, wv.y, wv.z, wv.w};
            #pragma unroll
            for (int i = 0; i < 4; i++)
                #pragma unroll
                for (int j = 0; j < 4; j++)
                    acc[i][j] += xr[i] * wr_[j];
        }
    }

    #pragma unroll
    for (int j = 0; j < 4; j++) {
        float4 o = make_float4(acc[0][j], acc[1][j], acc[2][j], acc[3][j]);
        *(float4*)&g_xz[(size_t)(t * NZ_ + n0 + nn + j) * B_ + b0] = o;
    }
}

// ---------------------------------------------------------------------------
// Kernel 2: persistent recurrence, 4 independent groups of 32 blocks
// (group g owns batches 4g..4g+3; block r owns units 8r..8r+7, warp = unit).
// Fully in-register per-warp epilogue: after the butterfly + one shfl_xor(16)
// cs-exchange, lanes 0..3 (= batches) compute the LSTM cell for this warp's
// unit entirely in registers (A, c, att, bias are lane-resident). Each warp
// publishes its 4 h values and its lane0 red.releases -> 256 arrivals/step.
// No d_s, no warp-0 serialization, only 2 syncthreads per step.
// ---------------------------------------------------------------------------
__global__ void __launch_bounds__(256)
rec_kernel(const float* __restrict__ h_init, const float* __restrict__ c_init,
           const float* __restrict__ out0,
           const float* __restrict__ Wih,  const float* __restrict__ Whh,
           const float* __restrict__ b_ih, const float* __restrict__ b_hh,
           float* __restrict__ dout)
{
    __shared__ float h_s[4 * H_];           // 4 KB: the group's 4 batches

    const int tid  = threadIdx.x;
    const int bid  = blockIdx.x;
    const int g    = bid >> 5;     // group 0..3 -> batches 4g..4g+3
    const int r    = bid & 31;     // unit block -> units 8r..8r+7
    const int u0   = r * 8;
    const int b0   = g * 4;
    const int w    = tid >> 5;     // warp = local unit
    const int lane = tid & 31;
    const int cs   = lane >> 4;    // 0 -> Whh, 1 -> Wa (Wih rows 256..511)
    const int kc   = lane & 15;    // k-pair base = 32*j + 2*kc
    const int u    = u0 + w;       // this warp's unit

    // packed weight slice in registers: wr2[c][j] = {W[k0][n], W[k0+1][n]}
    ull wr2[4][8];
    #pragma unroll
    for (int c = 0; c < 4; c++) {
        const int n = u + 256 * c;
        #pragma unroll
        for (int j = 0; j < 8; j++) {
            const int k0 = 32 * j + 2 * kc;
            float w0 = cs ? Wih[(size_t)(256 + k0) * NZ_ + n]
                          : Whh[(size_t)k0 * NZ_ + n];
            float w1 = cs ? Wih[(size_t)(256 + k0 + 1) * NZ_ + n]
                          : Whh[(size_t)(k0 + 1) * NZ_ + n];
            wr2[c][j] = pack2(w0, w1);
        }
    }

    // lane-resident cell state (lanes 0..3 = batches b0..b0+3)
    float A_r[4], bias_r[4], c_r = 0.f, att_r = 0.f;
    const int bme = b0 + lane;     // this lane's batch (valid when lane<4)
    if (lane < 4) {
        #pragma unroll
        for (int c = 0; c < 4; c++)
            bias_r[c] = b_ih[u + 256 * c] + b_hh[u + 256 * c];
        c_r   = c_init[bme * H_ + u];
        att_r = out0[bme * H_ + u];          // atten includes buf[0] = out0
    }

    // gemm: accO = this half's partial (lanes<16: Whh), accP = partner half
    auto do_gemm = [&](float accO[4][4], float accP[4][4]) {
        ull acc2[4][4];                      // [batch][gate]
        #pragma unroll
        for (int i = 0; i < 4; i++)
            #pragma unroll
            for (int c = 0; c < 4; c++) acc2[i][c] = pack2(0.f, 0.f);
        #pragma unroll
        for (int j = 0; j < 8; j++) {
            const int k0 = 32 * j + 2 * kc;
            ull h0 = *(const ull*)&h_s[0 * H_ + k0];
            ull h1 = *(const ull*)&h_s[1 * H_ + k0];
            ull h2 = *(const ull*)&h_s[2 * H_ + k0];
            ull h3 = *(const ull*)&h_s[3 * H_ + k0];
            #pragma unroll
            for (int c = 0; c < 4; c++) {
                ull wv = wr2[c][j];
                acc2[0][c] = fma2(h0, wv, acc2[0][c]);
                acc2[1][c] = fma2(h1, wv, acc2[1][c]);
                acc2[2][c] = fma2(h2, wv, acc2[2][c]);
                acc2[3][c] = fma2(h3, wv, acc2[3][c]);
            }
        }
        #pragma unroll
        for (int i = 0; i < 4; i++)
            #pragma unroll
            for (int c = 0; c < 4; c++) {
                float lo, hi; unpack2(acc2[i][c], lo, hi);
                accO[i][c] = lo + hi;
            }
        // butterfly over the 16 kc lanes (stays within cs halves)
        #pragma unroll
        for (int off = 8; off >= 1; off >>= 1)
            #pragma unroll
            for (int i = 0; i < 4; i++)
                #pragma unroll
                for (int c = 0; c < 4; c++)
                    accO[i][c] += __shfl_xor_sync(0xffffffffu, accO[i][c], off);
        // exchange cs halves: every lane gets the partner half too
        #pragma unroll
        for (int i = 0; i < 4; i++)
            #pragma unroll
            for (int c = 0; c < 4; c++)
                accP[i][c] = __shfl_xor_sync(0xffffffffu, accO[i][c], 16);
    };

    // ---- prestep: A_0 = out0 @ Wa  (out0 excluded from h recurrence) ----
    *(float4*)&h_s[tid * 4] = *(const float4*)&out0[b0 * H_ + tid * 4];
    __syncthreads();
    {
        float aO[4][4], aP[4][4];
        do_gemm(aO, aP);
        if (lane < 4) {                      // lanes<4 have cs=0 -> aP = Wa part
            #pragma unroll
            for (int c = 0; c < 4; c++) A_r[c] = aP[lane][c];
        }
    }
    __syncthreads();   // h_s reuse guard before t=0 stage

    // ---- main sequential loop (2 syncthreads per step) ----
    for (int t = 0; t < T_; t++) {
        // prefetch this step's xz early (lanes 0..3 of every warp)
        float xzv[4];
        if (lane < 4) {
            #pragma unroll
            for (int c = 0; c < 4; c++)
                xzv[c] = __ldcg(&g_xz[(size_t)(t * NZ_ + u + 256 * c) * B_ + bme]);
        }

        // wait: all 256 warps of this group finished step t-1
        if (t > 0 && tid == 0) {
            const unsigned* ctr = &g_arr[(g * T_ + (t - 1)) * 8];
            unsigned v;
            do {
                asm volatile("ld.acquire.gpu.global.u32 %0, [%1];"
                             : "=r"(v) : "l"(ctr) : "memory");
            } while (v < ARRV);
        }
        __syncthreads();   // (A) release + h_s WAR guard

        // stage h_{t-1} for the group's 4 batches: one float4 per thread
        {
            const float* hsrc = (t == 0) ? (h_init + b0 * H_)
                                         : (&g_h[(t - 1) & 1][b0 * H_]);
            float4 v = __ldcg((const float4*)(hsrc + tid * 4));
            *(float4*)&h_s[tid * 4] = v;
        }
        __syncthreads();   // (B)

        float dWh[4][4], dWa[4][4];          // for lanes<4: own=Whh, partner=Wa
        do_gemm(dWh, dWa);

        if (lane < 4) {
            float z[4];
            #pragma unroll
            for (int c = 0; c < 4; c++) {
                z[c] = xzv[c] + A_r[c] + dWa[lane][c] + dWh[lane][c] + bias_r[c];
                A_r[c] += dWa[lane][c];      // A_t = A_{t-1} + h_{t-1}@Wa
            }
            float si = fsigmoid(z[0]);
            float sf = fsigmoid(z[1]);
            float tg = ftanh_(z[2]);
            float so = fsigmoid(z[3]);
            float cn = sf * c_r + si * tg;
            float hn = so * ftanh_(cn);
            c_r = cn;
            if (t < T_ - 1) {
                __stcg(&g_h[t & 1][bme * H_ + u], hn);   // publish
                att_r += hn;                 // attens[-1] sums t<=T-2
            }
            if (t == T_ - 2) {
                dout[3 * 4096 + bme * H_ + u] = hn;      // h_prevs[-1]
                dout[4 * 4096 + bme * H_ + u] = cn;      // c_prevs[-1]
            }
            if (t == T_ - 1) {
                dout[0 * 4096 + bme * H_ + u] = hn;      // out_f (B,1,H)
                dout[1 * 4096 + bme * H_ + u] = hn;      // h_f   (1,B,H)
                dout[2 * 4096 + bme * H_ + u] = cn;      // c_f   (1,B,H)
            }
        }
        __syncwarp();                        // order this warp's h stores
        if (t < T_ - 1 && lane == 0) {
            // per-warp release-arrive (carries the warp's h stores)
            asm volatile("red.release.gpu.global.add.u32 [%0], %1;"
                         :: "l"(&g_arr[(g * T_ + t) * 8]), "r"(1u) : "memory");
        }
    }

    if (lane < 4)
        dout[5 * 4096 + bme * H_ + u] = att_r;           // attens[-1]
}

// ---------------------------------------------------------------------------
// inputs (metadata order): x, hidden_state, cell_state, out, Wih, Whh,
// b_ih, b_hh, W1, b1, W2, b2, W3, b3, bsize, time_step
// W1..b3 are dead (softmax over singleton axis makes weights == 1).
// ---------------------------------------------------------------------------
extern "C" void kernel_launch(void* const* d_in, const int* in_sizes, int n_in,
                              void* d_out, int out_size)
{
    const float* x       = (const float*)d_in[0];
    const float* h_init  = (const float*)d_in[1];
    const float* c_init  = (const float*)d_in[2];
    const float* out0    = (const float*)d_in[3];
    const float* Wih     = (const float*)d_in[4];
    const float* Whh     = (const float*)d_in[5];
    const float* b_ih    = (const float*)d_in[6];
    const float* b_hh    = (const float*)d_in[7];
    float* dout = (float*)d_out;

    dim3 g1(8, T_);
    xz_kernel<<<g1, 128>>>(x, Wih);
    rec_kernel<<<NBLK, 256>>>(h_init, c_init, out0, Wih, Whh, b_ih, b_hh, dout);
}